// round 2
// baseline (speedup 1.0000x reference)
#include <cuda_runtime.h>

// ============================================================================
// RNN_16587163698034 : 3-layer GRU stack (B=32, S=512) + Linear+ReLU
//
// Layout convention: batch (32) is the innermost dimension everywhere and maps
// to warp lanes -> coalesced 128B accesses for all activations/state.
//   xT  : [S][I0][32]
//   XG  : [S][3H][32]   (gate order r,z,n — input projection + bh)
//   Y   : [S][H][32]    (layer output, reused across layers)
//   h   : [H][32]       (hidden state, exchanged via L2 with .cg)
//
// Recurrence: persistent kernel, grid = #SMs, custom grid barrier.
//   per step: phase A computes r,z (writes rh=r*h and z), sync,
//             phase B computes n and h_new, sync.
// ============================================================================

#define DINL __device__ __forceinline__

static constexpr int S = 512;

// -------- static device scratch (no allocations allowed) --------
__device__ float g_xT[512 * 256 * 32];    // 16.8 MB
__device__ float g_XG[512 * 3072 * 32];   // 201 MB (sized for layer 1)
__device__ float g_Y [512 * 1024 * 32];   // 67 MB  (sized for layer 1)
__device__ float g_h [1024 * 32];
__device__ float g_rh[1024 * 32];
__device__ float g_z [1024 * 32];
__device__ unsigned g_bar_count = 0;
__device__ unsigned g_bar_gen   = 0;

DINL float sigmoidf_(float x) { return 1.0f / (1.0f + __expf(-x)); }

// Generation-counter grid barrier. Requires all blocks resident
// (grid <= #SMs, 1+ block fits per SM). Stores made visible via per-thread
// threadfence before arrive; post-barrier reads of shared state use .cg.
DINL void grid_sync_() {
    __threadfence();
    __syncthreads();
    if (threadIdx.x == 0) {
        volatile unsigned* genp = &g_bar_gen;
        unsigned my = *genp;
        if (atomicAdd(&g_bar_count, 1u) == gridDim.x - 1) {
            g_bar_count = 0u;
            __threadfence();
            *genp = my + 1u;
        } else {
            while (*genp == my) { __nanosleep(32); }
        }
    }
    __syncthreads();
}

// ---------------------------------------------------------------------------
// x [B=32][S=512][I=256]  ->  xT [S][I][32]
// ---------------------------------------------------------------------------
__global__ void transpose_x_kernel(const float* __restrict__ x) {
    __shared__ float sm[32][33];
    const int t  = blockIdx.x;
    const int i0 = blockIdx.y * 32;
    const int tx = threadIdx.x;   // 0..31
    const int ty = threadIdx.y;   // 0..7
    for (int b = ty; b < 32; b += 8)
        sm[b][tx] = x[(b * 512 + t) * 256 + i0 + tx];
    __syncthreads();
    for (int il = ty; il < 32; il += 8)
        g_xT[(t * 256 + i0 + il) * 32 + tx] = sm[tx][il];
}

// ---------------------------------------------------------------------------
// Input projection: XG[t][col][b] = bh[col] + sum_i IN[t][i][b] * Wi[col][i]
// warp task = (4 consecutive t) x (8 consecutive cols). FMA-bound by design:
// per 4 k: 16 coalesced x loads + 8 broadcast float4 w loads + 128 FFMA.
// ---------------------------------------------------------------------------
template <int IL, int HL3>
__global__ void __launch_bounds__(256) proj_kernel(const float* __restrict__ in,
                                                   const float* __restrict__ Wi,
                                                   const float* __restrict__ bh) {
    const int lane = threadIdx.x & 31;
    const int CG   = HL3 / 8;
    const int warp = blockIdx.x * 8 + (threadIdx.x >> 5);
    const int t0   = (warp / CG) * 4;
    const int c0   = (warp % CG) * 8;
    if (t0 >= S) return;

    float acc[4][8];
#pragma unroll
    for (int tt = 0; tt < 4; ++tt)
#pragma unroll
        for (int c = 0; c < 8; ++c) acc[tt][c] = 0.0f;

    const float* inb = in + lane;
    for (int k = 0; k < IL; k += 4) {
        float4 w[8];
#pragma unroll
        for (int c = 0; c < 8; ++c)
            w[c] = __ldg((const float4*)(Wi + (c0 + c) * IL + k));
#pragma unroll
        for (int kk = 0; kk < 4; ++kk) {
            float xv[4];
#pragma unroll
            for (int tt = 0; tt < 4; ++tt)
                xv[tt] = __ldg(&inb[((t0 + tt) * IL + k + kk) * 32]);
#pragma unroll
            for (int tt = 0; tt < 4; ++tt) {
#pragma unroll
                for (int c = 0; c < 8; ++c) {
                    float wv = (kk == 0) ? w[c].x : (kk == 1) ? w[c].y
                              : (kk == 2) ? w[c].z : w[c].w;
                    acc[tt][c] = fmaf(xv[tt], wv, acc[tt][c]);
                }
            }
        }
    }
#pragma unroll
    for (int c = 0; c < 8; ++c) {
        const float bias = __ldg(&bh[c0 + c]);
#pragma unroll
        for (int tt = 0; tt < 4; ++tt)
            g_XG[((t0 + tt) * HL3 + (c0 + c)) * 32 + lane] = acc[tt][c] + bias;
    }
}

// ---------------------------------------------------------------------------
// Recurrence (persistent). Gate order in Wh rows / XG cols: r, z, n.
//   r = sig(xr + h @ Whr^T); z = sig(xz + h @ Whz^T)
//   n = tanh(xn + (r*h) @ Whn^T); h = (1-z)*h + z*n
// ---------------------------------------------------------------------------
template <int HL>
__global__ void __launch_bounds__(256) rec_kernel(const float* __restrict__ Wh,
                                                  const float* __restrict__ h0,
                                                  const float* __restrict__ XG,
                                                  float* __restrict__ Y) {
    extern __shared__ float sm[];   // HL*32 floats
    const int tid    = threadIdx.x;
    const int lane   = tid & 31;
    const int nwarps = gridDim.x * 8;
    const int gwarp  = blockIdx.x * 8 + (tid >> 5);

    // init hidden state: h[j][b] = h0[j]
    for (int idx = blockIdx.x * 256 + tid; idx < HL * 32; idx += gridDim.x * 256)
        g_h[idx] = h0[idx >> 5];
    grid_sync_();

    for (int t = 0; t < S; ++t) {
        // ---- stage h into smem (.cg: must see other SMs' writes) ----
        for (int idx = tid * 4; idx < HL * 32; idx += 256 * 4) {
            float4 v = __ldcg((const float4*)(g_h + idx));
            *(float4*)(sm + idx) = v;
        }
        __syncthreads();

        const float* XGt = XG + t * (3 * HL) * 32 + lane;

        // ---- phase A: r and z (tasks = HL, each task = 2 cols of one gate) ----
        for (int task = gwarp; task < HL; task += nwarps) {
            const int gsel = (task >= HL / 2) ? 1 : 0;
            const int j0   = (task - gsel * (HL / 2)) * 2;
            const float* w0 = Wh + (gsel * HL + j0) * HL;
            const float* w1 = w0 + HL;
            const float* hp = sm + lane;
            float acc0 = 0.0f, acc1 = 0.0f;
#pragma unroll 2
            for (int k = 0; k < HL; k += 4) {
                float4 a = __ldg((const float4*)(w0 + k));
                float4 b = __ldg((const float4*)(w1 + k));
                float h0v = hp[(k + 0) * 32];
                float h1v = hp[(k + 1) * 32];
                float h2v = hp[(k + 2) * 32];
                float h3v = hp[(k + 3) * 32];
                acc0 = fmaf(a.x, h0v, acc0); acc1 = fmaf(b.x, h0v, acc1);
                acc0 = fmaf(a.y, h1v, acc0); acc1 = fmaf(b.y, h1v, acc1);
                acc0 = fmaf(a.z, h2v, acc0); acc1 = fmaf(b.z, h2v, acc1);
                acc0 = fmaf(a.w, h3v, acc0); acc1 = fmaf(b.w, h3v, acc1);
            }
            const float xg0 = __ldg(&XGt[(gsel * HL + j0) * 32]);
            const float xg1 = __ldg(&XGt[(gsel * HL + j0 + 1) * 32]);
            const float v0 = sigmoidf_(xg0 + acc0);
            const float v1 = sigmoidf_(xg1 + acc1);
            if (gsel == 0) {
                __stcg(&g_rh[(j0    ) * 32 + lane], v0 * (sm + lane)[(j0    ) * 32]);
                __stcg(&g_rh[(j0 + 1) * 32 + lane], v1 * (sm + lane)[(j0 + 1) * 32]);
            } else {
                __stcg(&g_z[(j0    ) * 32 + lane], v0);
                __stcg(&g_z[(j0 + 1) * 32 + lane], v1);
            }
        }
        grid_sync_();

        // ---- stage rh into smem ----
        for (int idx = tid * 4; idx < HL * 32; idx += 256 * 4) {
            float4 v = __ldcg((const float4*)(g_rh + idx));
            *(float4*)(sm + idx) = v;
        }
        __syncthreads();

        // ---- phase B: n + state update (tasks = HL/2, 2 cols each) ----
        for (int task = gwarp; task < HL / 2; task += nwarps) {
            const int j0 = task * 2;
            const float* w0 = Wh + (2 * HL + j0) * HL;
            const float* w1 = w0 + HL;
            const float* rp = sm + lane;
            float acc0 = 0.0f, acc1 = 0.0f;
#pragma unroll 2
            for (int k = 0; k < HL; k += 4) {
                float4 a = __ldg((const float4*)(w0 + k));
                float4 b = __ldg((const float4*)(w1 + k));
                float r0v = rp[(k + 0) * 32];
                float r1v = rp[(k + 1) * 32];
                float r2v = rp[(k + 2) * 32];
                float r3v = rp[(k + 3) * 32];
                acc0 = fmaf(a.x, r0v, acc0); acc1 = fmaf(b.x, r0v, acc1);
                acc0 = fmaf(a.y, r1v, acc0); acc1 = fmaf(b.y, r1v, acc1);
                acc0 = fmaf(a.z, r2v, acc0); acc1 = fmaf(b.z, r2v, acc1);
                acc0 = fmaf(a.w, r3v, acc0); acc1 = fmaf(b.w, r3v, acc1);
            }
            const float xn0 = __ldg(&XGt[(2 * HL + j0) * 32]);
            const float xn1 = __ldg(&XGt[(2 * HL + j0 + 1) * 32]);
            const float n0 = tanhf(xn0 + acc0);
            const float n1 = tanhf(xn1 + acc1);
            const float z0 = __ldcg(&g_z[(j0    ) * 32 + lane]);
            const float z1 = __ldcg(&g_z[(j0 + 1) * 32 + lane]);
            const float hv0 = __ldcg(&g_h[(j0    ) * 32 + lane]);
            const float hv1 = __ldcg(&g_h[(j0 + 1) * 32 + lane]);
            const float hn0 = (1.0f - z0) * hv0 + z0 * n0;
            const float hn1 = (1.0f - z1) * hv1 + z1 * n1;
            __stcg(&g_h[(j0    ) * 32 + lane], hn0);
            __stcg(&g_h[(j0 + 1) * 32 + lane], hn1);
            Y[(t * HL + j0    ) * 32 + lane] = hn0;
            Y[(t * HL + j0 + 1) * 32 + lane] = hn1;
        }
        grid_sync_();
    }
}

// ---------------------------------------------------------------------------
// out[b][t][o] = relu(bo[o] + sum_k Y[t][k][b] * Wo[o][k]),  HL=512, O=256
// warp task = (t, 8-col o-chunk); lanes = b.
// ---------------------------------------------------------------------------
__global__ void __launch_bounds__(256) out_kernel(const float* __restrict__ Wo,
                                                  const float* __restrict__ bo,
                                                  float* __restrict__ out) {
    const int lane = threadIdx.x & 31;
    const int warp = blockIdx.x * 8 + (threadIdx.x >> 5);
    const int t    = warp >> 5;          // 512 * 32 tasks
    const int o0   = (warp & 31) * 8;
    if (t >= S) return;

    float acc[8];
#pragma unroll
    for (int c = 0; c < 8; ++c) acc[c] = 0.0f;

    const float* yb = g_Y + lane;
    for (int k = 0; k < 512; k += 4) {
        float yv0 = yb[(t * 512 + k + 0) * 32];
        float yv1 = yb[(t * 512 + k + 1) * 32];
        float yv2 = yb[(t * 512 + k + 2) * 32];
        float yv3 = yb[(t * 512 + k + 3) * 32];
#pragma unroll
        for (int c = 0; c < 8; ++c) {
            float4 w = __ldg((const float4*)(Wo + (o0 + c) * 512 + k));
            acc[c] = fmaf(yv0, w.x, acc[c]);
            acc[c] = fmaf(yv1, w.y, acc[c]);
            acc[c] = fmaf(yv2, w.z, acc[c]);
            acc[c] = fmaf(yv3, w.w, acc[c]);
        }
    }
#pragma unroll
    for (int c = 0; c < 8; ++c) {
        float v = acc[c] + __ldg(&bo[o0 + c]);
        out[(lane * 512 + t) * 256 + o0 + c] = fmaxf(v, 0.0f);
    }
}

// ---------------------------------------------------------------------------
extern "C" void kernel_launch(void* const* d_in, const int* in_sizes, int n_in,
                              void* d_out, int out_size) {
    const float* x   = (const float*)d_in[0];
    const float* Wi0 = (const float*)d_in[1];
    const float* Wh0 = (const float*)d_in[2];
    const float* bh0 = (const float*)d_in[3];
    const float* h00 = (const float*)d_in[4];
    const float* Wi1 = (const float*)d_in[5];
    const float* Wh1 = (const float*)d_in[6];
    const float* bh1 = (const float*)d_in[7];
    const float* h01 = (const float*)d_in[8];
    const float* Wi2 = (const float*)d_in[9];
    const float* Wh2 = (const float*)d_in[10];
    const float* bh2 = (const float*)d_in[11];
    const float* h02 = (const float*)d_in[12];
    const float* Wo  = (const float*)d_in[13];
    const float* bo  = (const float*)d_in[14];
    float* out = (float*)d_out;

    int nb = 148;
    cudaDeviceGetAttribute(&nb, cudaDevAttrMultiProcessorCount, 0);

    cudaFuncSetAttribute(rec_kernel<512>,  cudaFuncAttributeMaxDynamicSharedMemorySize,
                         512 * 32 * (int)sizeof(float));
    cudaFuncSetAttribute(rec_kernel<1024>, cudaFuncAttributeMaxDynamicSharedMemorySize,
                         1024 * 32 * (int)sizeof(float));

    void *pxT = nullptr, *pXG = nullptr, *pY = nullptr;
    cudaGetSymbolAddress(&pxT, g_xT);
    cudaGetSymbolAddress(&pXG, g_XG);
    cudaGetSymbolAddress(&pY,  g_Y);
    const float* fxT = (const float*)pxT;
    const float* fXG = (const float*)pXG;
    float*       fY  = (float*)pY;

    // x -> xT
    transpose_x_kernel<<<dim3(512, 8), dim3(32, 8)>>>(x);

    // ---- layer 0: I=256, H=512 ----
    proj_kernel<256, 1536><<<(128 * (1536 / 8)) / 8, 256>>>(fxT, Wi0, bh0);
    rec_kernel<512><<<nb, 256, 512 * 32 * sizeof(float)>>>(Wh0, h00, fXG, fY);

    // ---- layer 1: I=512, H=1024 ----
    proj_kernel<512, 3072><<<(128 * (3072 / 8)) / 8, 256>>>(fY, Wi1, bh1);
    rec_kernel<1024><<<nb, 256, 1024 * 32 * sizeof(float)>>>(Wh1, h01, fXG, fY);

    // ---- layer 2: I=1024, H=512 ----
    proj_kernel<1024, 1536><<<(128 * (1536 / 8)) / 8, 256>>>(fY, Wi2, bh2);
    rec_kernel<512><<<nb, 256, 512 * 32 * sizeof(float)>>>(Wh2, h02, fXG, fY);

    // ---- output projection + relu ----
    out_kernel<<<(512 * 32) / 8, 256>>>(Wo, bo, out);

    (void)in_sizes; (void)n_in; (void)out_size;
}

// round 3
// speedup vs baseline: 3.3385x; 3.3385x over previous
#include <cuda_runtime.h>

// ============================================================================
// RNN_16587163698034 : 3-layer GRU stack (B=32, S=512) + Linear+ReLU
//
// R2: recurrence rewritten as weight-stationary persistent kernel.
//  - 128 blocks; block owns cpg=H/128 output cols per gate; Wh slice cached in
//    smem as float4 column-quads (one broadcast LDS.128 serves 4 cols/k).
//  - fma.rn.f32x2 packed FMA: col-pair accumulators share a packed h operand.
//  - h / rh exchanged via L2 (st.cg writers, cp.async.cg readers), staged in
//    4 double-buffered chunks overlapping compute.
//  - 2 release/acquire grid barriers per step, local-epoch based, with a
//    closing reset so state is clean across kernels and graph replays.
//  - z and own-h stay in smem (zbuf / hown), never round-trip through L2.
// ============================================================================

#define DINL __device__ __forceinline__
typedef unsigned long long ull;

static constexpr int S  = 512;
static constexpr int NB = 128;   // persistent blocks (<= SM count, all resident)

// -------- static device scratch (no allocations allowed) --------
__device__ float g_xT[512 * 256 * 32];    // 16.8 MB
__device__ float g_XG[512 * 3072 * 32];   // 201 MB (sized for layer 1)
__device__ float g_Y [512 * 1024 * 32];   // 67 MB  (sized for layer 1)
__device__ float g_h [1024 * 32];
__device__ float g_rh[1024 * 32];
__device__ unsigned g_bar_count = 0;
__device__ unsigned g_bar_gen   = 0;

DINL float sigmoidf_(float x) { return 1.0f / (1.0f + __expf(-x)); }

// ---- packed f32x2 helpers ----
DINL ull ffma2(ull a, ull b, ull c) {
    ull d;
    asm("fma.rn.f32x2 %0, %1, %2, %3;" : "=l"(d) : "l"(a), "l"(b), "l"(c));
    return d;
}
DINL ull fadd2(ull a, ull b) {
    ull d;
    asm("add.rn.f32x2 %0, %1, %2;" : "=l"(d) : "l"(a), "l"(b));
    return d;
}
DINL ull pack2(float x) {
    ull d;
    asm("mov.b64 %0, {%1, %1};" : "=l"(d) : "f"(x));
    return d;
}
DINL void unpack2(ull v, float& a, float& b) {
    asm("mov.b64 {%0, %1}, %2;" : "=f"(a), "=f"(b) : "l"(v));
}

// ---- cp.async helpers ----
template <int N>
DINL void cp_wait() { asm volatile("cp.async.wait_group %0;" :: "n"(N) : "memory"); }

DINL void stage_chunk(const float* __restrict__ gsrc, float* __restrict__ dst,
                      int n16, int tid) {
    unsigned d = (unsigned)__cvta_generic_to_shared(dst);
    for (int e = tid; e < n16; e += 256)
        asm volatile("cp.async.cg.shared.global [%0], [%1], 16;"
                     :: "r"(d + e * 16), "l"(gsrc + e * 4) : "memory");
    asm volatile("cp.async.commit_group;" ::: "memory");
}

// ---- grid barrier: release/acquire, local epoch, closing reset ----
DINL void grid_bar(unsigned target, bool closing) {
    __syncthreads();
    if (threadIdx.x == 0) {
        unsigned old, one = 1;
        asm volatile("atom.acq_rel.gpu.global.add.u32 %0, [%1], %2;"
                     : "=r"(old) : "l"(&g_bar_count), "r"(one) : "memory");
        if (old == (unsigned)gridDim.x - 1) {
            unsigned zero = 0;
            asm volatile("st.relaxed.gpu.global.u32 [%0], %1;"
                         :: "l"(&g_bar_count), "r"(zero) : "memory");
            unsigned nv = closing ? 0u : target;
            asm volatile("st.release.gpu.global.u32 [%0], %1;"
                         :: "l"(&g_bar_gen), "r"(nv) : "memory");
        } else {
            unsigned g;
            do {
                asm volatile("ld.acquire.gpu.global.u32 %0, [%1];"
                             : "=r"(g) : "l"(&g_bar_gen) : "memory");
            } while (closing ? (g != 0u) : (g < target));
        }
    }
    __syncthreads();
}

// ---------------------------------------------------------------------------
// One phase of the recurrence GEMM: acc[q] += W_quad[q] * src (k in [0,HL)).
// src staged from L2 in 4 double-buffered chunks via cp.async.cg.
// Every warp covers k-slice [w*KW, (w+1)*KW) of each chunk, all NQ quads.
// ---------------------------------------------------------------------------
template <int HL, int NQ, int QOFF, bool COPY_HOWN>
DINL void gemm_phase(const float* __restrict__ gsrc,
                     const float* __restrict__ wq,   // smem quads base
                     float* __restrict__ hbuf,       // smem 2*CHK*32
                     float* __restrict__ hown,       // smem cpg*32
                     ull acc[NQ][2],
                     int tid, int lane, int warp, int jb) {
    constexpr int CHK = HL / 4;
    constexpr int KW  = CHK / 8;
    constexpr int cpg = HL / NB;
    constexpr int N16 = CHK * 8;

#pragma unroll
    for (int q = 0; q < NQ; ++q) { acc[q][0] = 0ull; acc[q][1] = 0ull; }

    stage_chunk(gsrc,            hbuf,            N16, tid);
    stage_chunk(gsrc + CHK * 32, hbuf + CHK * 32, N16, tid);

#pragma unroll
    for (int c = 0; c < 4; ++c) {
        if (c < 3) cp_wait<1>(); else cp_wait<0>();
        __syncthreads();
        if (COPY_HOWN && c == jb / CHK) {
            if (tid < cpg * 32)
                hown[tid] = hbuf[(c & 1) * CHK * 32 + (jb - c * CHK) * 32 + tid];
        }
        const float* hb = hbuf + (c & 1) * CHK * 32;
        const int kb = warp * KW;
#pragma unroll 8
        for (int kk = 0; kk < KW; ++kk) {
            const int kc = kb + kk;            // chunk-local k
            const int k  = c * CHK + kc;       // global k
            ull h2 = pack2(hb[kc * 32 + lane]);
#pragma unroll
            for (int q = 0; q < NQ; ++q) {
                ulonglong2 wv = *(const ulonglong2*)(wq + ((size_t)(QOFF + q) * HL + k) * 4);
                acc[q][0] = ffma2(h2, wv.x, acc[q][0]);
                acc[q][1] = ffma2(h2, wv.y, acc[q][1]);
            }
        }
        __syncthreads();
        if (c + 2 < 4)
            stage_chunk(gsrc + (c + 2) * CHK * 32, hbuf + (c & 1) * CHK * 32, N16, tid);
    }
}

// ---------------------------------------------------------------------------
// Persistent recurrence kernel. Gate order r,z,n.
//   r = sig(xr + h@Whr^T); z = sig(xz + h@Whz^T)
//   n = tanh(xn + (r*h)@Whn^T); h = (1-z)h + z*n
// ---------------------------------------------------------------------------
template <int HL>
__global__ void __launch_bounds__(256, 1) rec2_kernel(const float* __restrict__ Wh,
                                                      const float* __restrict__ h0,
                                                      const float* __restrict__ XG,
                                                      float* __restrict__ Y) {
    constexpr int cpg = HL / NB;       // cols per gate per block (4 or 8)
    constexpr int CHK = HL / 4;
    constexpr int NQT = 3 * cpg / 4;   // total quads (r,z,n)
    constexpr int NQA = cpg / 2;       // phase A quads (r+z)
    constexpr int NQB = cpg / 4;       // phase B quads (n)
    constexpr int PA  = cpg;           // phase A col-pairs
    constexpr int PB  = cpg / 2;

    extern __shared__ char smem[];
    float* wq   = (float*)smem;                                        // NQT*HL float4
    float* hbuf = (float*)(smem + (size_t)NQT * HL * 16);              // 2*CHK*32
    ull*   scr  = (ull*)(smem + (size_t)NQT * HL * 16 + 2 * CHK * 32 * 4);
    float* zbuf = (float*)((char*)scr + 8 * PA * 32 * 8);
    float* hown = zbuf + cpg * 32;

    const int tid  = threadIdx.x;
    const int lane = tid & 31;
    const int warp = tid >> 5;
    const int jb   = blockIdx.x * cpg;

    // ---- load weight quads: wq[q][k] = {W[c0..c0+3][k]} (interleaved) ----
    for (int idx = tid; idx < NQT * HL; idx += 256) {
        const int q = idx / HL, k = idx - q * HL;
        const int g = q / (cpg / 4), qq = q % (cpg / 4);
        const float* r = Wh + (size_t)(g * HL + jb + qq * 4) * HL + k;
        float4 v = make_float4(r[0], r[HL], r[2 * HL], r[3 * HL]);
        *(float4*)(wq + ((size_t)q * HL + k) * 4) = v;
    }
    // ---- init own slice of h ----
    if (tid < cpg * 32) __stcg(&g_h[jb * 32 + tid], __ldg(&h0[jb + (tid >> 5)]));

    unsigned ep = 1;
    grid_bar(ep, false); ++ep;

    for (int t = 0; t < S; ++t) {
        // ================= PHASE A : r, z =================
        ull accA[NQA][2];
        gemm_phase<HL, NQA, 0, true>(g_h, wq, hbuf, hown, accA, tid, lane, warp, jb);
#pragma unroll
        for (int q = 0; q < NQA; ++q) {
            scr[(warp * PA + 2 * q    ) * 32 + lane] = accA[q][0];
            scr[(warp * PA + 2 * q + 1) * 32 + lane] = accA[q][1];
        }
        __syncthreads();
        if (warp < PA) {
            ull s = scr[warp * 32 + lane];
#pragma unroll
            for (int wi = 1; wi < 8; ++wi) s = fadd2(s, scr[(wi * PA + warp) * 32 + lane]);
            float a0, a1; unpack2(s, a0, a1);
            const int g  = warp / (cpg / 2);
            const int l0 = (warp % (cpg / 2)) * 2;
            const int j  = jb + l0;
            const float* xg = XG + ((size_t)t * 3 * HL + (size_t)g * HL + j) * 32 + lane;
            const float v0 = sigmoidf_(__ldg(xg)      + a0);
            const float v1 = sigmoidf_(__ldg(xg + 32) + a1);
            if (g == 0) {
                __stcg(&g_rh[(j    ) * 32 + lane], v0 * hown[(l0    ) * 32 + lane]);
                __stcg(&g_rh[(j + 1) * 32 + lane], v1 * hown[(l0 + 1) * 32 + lane]);
            } else {
                zbuf[(l0    ) * 32 + lane] = v0;
                zbuf[(l0 + 1) * 32 + lane] = v1;
            }
        }
        grid_bar(ep, false); ++ep;

        // ================= PHASE B : n, update =================
        ull accB[NQB][2];
        gemm_phase<HL, NQB, cpg / 2, false>(g_rh, wq, hbuf, hown, accB, tid, lane, warp, jb);
#pragma unroll
        for (int q = 0; q < NQB; ++q) {
            scr[(warp * PB + 2 * q    ) * 32 + lane] = accB[q][0];
            scr[(warp * PB + 2 * q + 1) * 32 + lane] = accB[q][1];
        }
        __syncthreads();
        if (warp < PB) {
            ull s = scr[warp * 32 + lane];
#pragma unroll
            for (int wi = 1; wi < 8; ++wi) s = fadd2(s, scr[(wi * PB + warp) * 32 + lane]);
            float a0, a1; unpack2(s, a0, a1);
            const int l0 = warp * 2;
            const int j  = jb + l0;
            const float* xg = XG + ((size_t)t * 3 * HL + 2 * (size_t)HL + j) * 32 + lane;
            const float n0 = tanhf(__ldg(xg)      + a0);
            const float n1 = tanhf(__ldg(xg + 32) + a1);
            const float z0 = zbuf[(l0    ) * 32 + lane];
            const float z1 = zbuf[(l0 + 1) * 32 + lane];
            const float o0 = hown[(l0    ) * 32 + lane];
            const float o1 = hown[(l0 + 1) * 32 + lane];
            const float hn0 = (1.0f - z0) * o0 + z0 * n0;
            const float hn1 = (1.0f - z1) * o1 + z1 * n1;
            __stcg(&g_h[(j    ) * 32 + lane], hn0);
            __stcg(&g_h[(j + 1) * 32 + lane], hn1);
            Y[((size_t)t * HL + j    ) * 32 + lane] = hn0;
            Y[((size_t)t * HL + j + 1) * 32 + lane] = hn1;
        }
        grid_bar(ep, t == S - 1); ++ep;
    }
}

// ---------------------------------------------------------------------------
// x [B=32][S=512][I=256]  ->  xT [S][I][32]
// ---------------------------------------------------------------------------
__global__ void transpose_x_kernel(const float* __restrict__ x) {
    __shared__ float sm[32][33];
    const int t  = blockIdx.x;
    const int i0 = blockIdx.y * 32;
    const int tx = threadIdx.x;
    const int ty = threadIdx.y;
    for (int b = ty; b < 32; b += 8)
        sm[b][tx] = x[(b * 512 + t) * 256 + i0 + tx];
    __syncthreads();
    for (int il = ty; il < 32; il += 8)
        g_xT[(t * 256 + i0 + il) * 32 + tx] = sm[tx][il];
}

// ---------------------------------------------------------------------------
// Input projection: XG[t][col][b] = bh[col] + sum_i IN[t][i][b] * Wi[col][i]
// ---------------------------------------------------------------------------
template <int IL, int HL3>
__global__ void __launch_bounds__(256) proj_kernel(const float* __restrict__ in,
                                                   const float* __restrict__ Wi,
                                                   const float* __restrict__ bh) {
    const int lane = threadIdx.x & 31;
    const int CG   = HL3 / 8;
    const int warp = blockIdx.x * 8 + (threadIdx.x >> 5);
    const int t0   = (warp / CG) * 4;
    const int c0   = (warp % CG) * 8;
    if (t0 >= S) return;

    float acc[4][8];
#pragma unroll
    for (int tt = 0; tt < 4; ++tt)
#pragma unroll
        for (int c = 0; c < 8; ++c) acc[tt][c] = 0.0f;

    const float* inb = in + lane;
    for (int k = 0; k < IL; k += 4) {
        float4 w[8];
#pragma unroll
        for (int c = 0; c < 8; ++c)
            w[c] = __ldg((const float4*)(Wi + (c0 + c) * IL + k));
#pragma unroll
        for (int kk = 0; kk < 4; ++kk) {
            float xv[4];
#pragma unroll
            for (int tt = 0; tt < 4; ++tt)
                xv[tt] = __ldg(&inb[((t0 + tt) * IL + k + kk) * 32]);
#pragma unroll
            for (int tt = 0; tt < 4; ++tt) {
#pragma unroll
                for (int c = 0; c < 8; ++c) {
                    float wv = (kk == 0) ? w[c].x : (kk == 1) ? w[c].y
                              : (kk == 2) ? w[c].z : w[c].w;
                    acc[tt][c] = fmaf(xv[tt], wv, acc[tt][c]);
                }
            }
        }
    }
#pragma unroll
    for (int c = 0; c < 8; ++c) {
        const float bias = __ldg(&bh[c0 + c]);
#pragma unroll
        for (int tt = 0; tt < 4; ++tt)
            g_XG[((size_t)(t0 + tt) * HL3 + (c0 + c)) * 32 + lane] = acc[tt][c] + bias;
    }
}

// ---------------------------------------------------------------------------
// out[b][t][o] = relu(bo[o] + sum_k Y[t][k][b] * Wo[o][k]),  HL=512, O=256
// ---------------------------------------------------------------------------
__global__ void __launch_bounds__(256) out_kernel(const float* __restrict__ Wo,
                                                  const float* __restrict__ bo,
                                                  float* __restrict__ out) {
    const int lane = threadIdx.x & 31;
    const int warp = blockIdx.x * 8 + (threadIdx.x >> 5);
    const int t    = warp >> 5;
    const int o0   = (warp & 31) * 8;
    if (t >= S) return;

    float acc[8];
#pragma unroll
    for (int c = 0; c < 8; ++c) acc[c] = 0.0f;

    const float* yb = g_Y + lane;
    for (int k = 0; k < 512; k += 4) {
        float yv0 = yb[(t * 512 + k + 0) * 32];
        float yv1 = yb[(t * 512 + k + 1) * 32];
        float yv2 = yb[(t * 512 + k + 2) * 32];
        float yv3 = yb[(t * 512 + k + 3) * 32];
#pragma unroll
        for (int c = 0; c < 8; ++c) {
            float4 w = __ldg((const float4*)(Wo + (o0 + c) * 512 + k));
            acc[c] = fmaf(yv0, w.x, acc[c]);
            acc[c] = fmaf(yv1, w.y, acc[c]);
            acc[c] = fmaf(yv2, w.z, acc[c]);
            acc[c] = fmaf(yv3, w.w, acc[c]);
        }
    }
#pragma unroll
    for (int c = 0; c < 8; ++c) {
        float v = acc[c] + __ldg(&bo[o0 + c]);
        out[(lane * 512 + t) * 256 + o0 + c] = fmaxf(v, 0.0f);
    }
}

// ---------------------------------------------------------------------------
extern "C" void kernel_launch(void* const* d_in, const int* in_sizes, int n_in,
                              void* d_out, int out_size) {
    const float* x   = (const float*)d_in[0];
    const float* Wi0 = (const float*)d_in[1];
    const float* Wh0 = (const float*)d_in[2];
    const float* bh0 = (const float*)d_in[3];
    const float* h00 = (const float*)d_in[4];
    const float* Wi1 = (const float*)d_in[5];
    const float* Wh1 = (const float*)d_in[6];
    const float* bh1 = (const float*)d_in[7];
    const float* h01 = (const float*)d_in[8];
    const float* Wi2 = (const float*)d_in[9];
    const float* Wh2 = (const float*)d_in[10];
    const float* bh2 = (const float*)d_in[11];
    const float* h02 = (const float*)d_in[12];
    const float* Wo  = (const float*)d_in[13];
    const float* bo  = (const float*)d_in[14];
    float* out = (float*)d_out;

    // smem sizes: wq + hbuf + scratch + zbuf + hown
    auto smem_for = [](int HL) {
        int cpg = HL / NB, CHK = HL / 4, NQT = 3 * cpg / 4;
        return NQT * HL * 16 + 2 * CHK * 32 * 4 + 8 * cpg * 32 * 8 + 2 * cpg * 32 * 4;
    };
    const int SM512  = smem_for(512);    //  66,560 B
    const int SM1024 = smem_for(1024);   // 182,272 B
    cudaFuncSetAttribute(rec2_kernel<512>,  cudaFuncAttributeMaxDynamicSharedMemorySize, SM512);
    cudaFuncSetAttribute(rec2_kernel<1024>, cudaFuncAttributeMaxDynamicSharedMemorySize, SM1024);

    void *pxT = nullptr, *pXG = nullptr, *pY = nullptr;
    cudaGetSymbolAddress(&pxT, g_xT);
    cudaGetSymbolAddress(&pXG, g_XG);
    cudaGetSymbolAddress(&pY,  g_Y);
    const float* fxT = (const float*)pxT;
    const float* fXG = (const float*)pXG;
    float*       fY  = (float*)pY;

    transpose_x_kernel<<<dim3(512, 8), dim3(32, 8)>>>(x);

    // ---- layer 0: I=256, H=512 ----
    proj_kernel<256, 1536><<<(128 * (1536 / 8)) / 8, 256>>>(fxT, Wi0, bh0);
    rec2_kernel<512><<<NB, 256, SM512>>>(Wh0, h00, fXG, fY);

    // ---- layer 1: I=512, H=1024 ----
    proj_kernel<512, 3072><<<(128 * (3072 / 8)) / 8, 256>>>(fY, Wi1, bh1);
    rec2_kernel<1024><<<NB, 256, SM1024>>>(Wh1, h01, fXG, fY);

    // ---- layer 2: I=1024, H=512 ----
    proj_kernel<1024, 1536><<<(128 * (1536 / 8)) / 8, 256>>>(fY, Wi2, bh2);
    rec2_kernel<512><<<NB, 256, SM512>>>(Wh2, h02, fXG, fY);

    // ---- output projection + relu ----
    out_kernel<<<(512 * 32) / 8, 256>>>(Wo, bo, out);

    (void)in_sizes; (void)n_in; (void)out_size;
}